// round 1
// baseline (speedup 1.0000x reference)
#include <cuda_runtime.h>
#include <math.h>

#define NN 500000
#define NE 8000000

// Scratch (device globals — no allocation in kernel_launch)
__device__ float g_deg[NN];
__device__ float g_dinv[NN];
__device__ float g_p[NN];     // x*dinv
__device__ float g_a1[NN];    // scatter accumulator layer 1
__device__ float g_q[2*NN];   // z*dinv per node (2 floats)
__device__ float g_a2[2*NN];  // scatter accumulator layer 2

// ---------------- init: deg=1 (self loop), a1=0, a2=0 ----------------
__global__ void k_init(int n) {
    int i = blockIdx.x * blockDim.x + threadIdx.x;
    if (i < n) { g_deg[i] = 1.0f; g_a1[i] = 0.0f; }
    if (i < 2 * n) { g_a2[i] = 0.0f; }
}

// ---------------- count in-degree over dst ----------------
__global__ void k_count(const int* __restrict__ dst, int ne) {
    int i = blockIdx.x * blockDim.x + threadIdx.x;
    int e = i * 4;
    if (e + 4 <= ne) {
        int4 d = *reinterpret_cast<const int4*>(dst + e);
        atomicAdd(&g_deg[d.x], 1.0f);
        atomicAdd(&g_deg[d.y], 1.0f);
        atomicAdd(&g_deg[d.z], 1.0f);
        atomicAdd(&g_deg[d.w], 1.0f);
    } else {
        for (; e < ne; e++) atomicAdd(&g_deg[dst[e]], 1.0f);
    }
}

// ---------------- dinv = rsqrt(deg); p = x * dinv ----------------
__global__ void k_prep(const float* __restrict__ x, int n) {
    int i = blockIdx.x * blockDim.x + threadIdx.x;
    if (i < n) {
        float dv = rsqrtf(g_deg[i]);
        g_dinv[i] = dv;
        g_p[i] = x[i] * dv;
    }
}

// ---------------- layer-1 scalar scatter: a1[dst] += p[src] ----------------
__global__ void k_scatter1(const int* __restrict__ src,
                           const int* __restrict__ dst, int ne) {
    int i = blockIdx.x * blockDim.x + threadIdx.x;
    int e = i * 4;
    if (e + 4 <= ne) {
        int4 s = *reinterpret_cast<const int4*>(src + e);
        int4 d = *reinterpret_cast<const int4*>(dst + e);
        float p0 = g_p[s.x], p1 = g_p[s.y], p2 = g_p[s.z], p3 = g_p[s.w];
        atomicAdd(&g_a1[d.x], p0);
        atomicAdd(&g_a1[d.y], p1);
        atomicAdd(&g_a1[d.z], p2);
        atomicAdd(&g_a1[d.w], p3);
    } else {
        for (; e < ne; e++) atomicAdd(&g_a1[dst[e]], g_p[src[e]]);
    }
}

// ---------------- per-node MLP: s1 -> relu(s1*W1+b1) @ W2 -> q = z*dinv ----
__global__ void k_node(const float* __restrict__ W1,
                       const float* __restrict__ b1,
                       const float* __restrict__ W2, int n) {
    __shared__ float sW1[16], sb1[16], sW2[32];
    int t = threadIdx.x;
    if (t < 16) { sW1[t] = W1[t]; sb1[t] = b1[t]; }
    if (t < 32) { sW2[t] = W2[t]; }
    __syncthreads();
    int i = blockIdx.x * blockDim.x + t;
    if (i < n) {
        float dv = g_dinv[i];
        float s1 = dv * (g_a1[i] + g_p[i]);
        float z0 = 0.0f, z1 = 0.0f;
        #pragma unroll
        for (int k = 0; k < 16; k++) {
            float h = fmaxf(fmaf(s1, sW1[k], sb1[k]), 0.0f);
            z0 = fmaf(h, sW2[2 * k + 0], z0);
            z1 = fmaf(h, sW2[2 * k + 1], z1);
        }
        float2 q = make_float2(z0 * dv, z1 * dv);
        *reinterpret_cast<float2*>(g_q + 2 * i) = q;
    }
}

// ---------------- layer-2 2-float scatter: a2[dst] += q[src] ----------------
__global__ void k_scatter2(const int* __restrict__ src,
                           const int* __restrict__ dst, int ne) {
    int i = blockIdx.x * blockDim.x + threadIdx.x;
    int e = i * 4;
    if (e + 4 <= ne) {
        int4 s = *reinterpret_cast<const int4*>(src + e);
        int4 d = *reinterpret_cast<const int4*>(dst + e);
        float2 q0 = *reinterpret_cast<const float2*>(g_q + 2 * s.x);
        float2 q1 = *reinterpret_cast<const float2*>(g_q + 2 * s.y);
        float2 q2 = *reinterpret_cast<const float2*>(g_q + 2 * s.z);
        float2 q3 = *reinterpret_cast<const float2*>(g_q + 2 * s.w);
        atomicAdd(&g_a2[2 * d.x + 0], q0.x); atomicAdd(&g_a2[2 * d.x + 1], q0.y);
        atomicAdd(&g_a2[2 * d.y + 0], q1.x); atomicAdd(&g_a2[2 * d.y + 1], q1.y);
        atomicAdd(&g_a2[2 * d.z + 0], q2.x); atomicAdd(&g_a2[2 * d.z + 1], q2.y);
        atomicAdd(&g_a2[2 * d.w + 0], q3.x); atomicAdd(&g_a2[2 * d.w + 1], q3.y);
    } else {
        for (; e < ne; e++) {
            int s = src[e], d = dst[e];
            atomicAdd(&g_a2[2 * d + 0], g_q[2 * s + 0]);
            atomicAdd(&g_a2[2 * d + 1], g_q[2 * s + 1]);
        }
    }
}

// ---------------- finalize: out = log_softmax(dinv*(a2+q) + b2) ----------------
__global__ void k_final(const float* __restrict__ b2, float* __restrict__ out, int n) {
    int i = blockIdx.x * blockDim.x + threadIdx.x;
    if (i < n) {
        float dv = g_dinv[i];
        float2 q = *reinterpret_cast<const float2*>(g_q + 2 * i);
        float2 a = *reinterpret_cast<const float2*>(g_a2 + 2 * i);
        float v0 = fmaf(dv, a.x + q.x, b2[0]);
        float v1 = fmaf(dv, a.y + q.y, b2[1]);
        float m = fmaxf(v0, v1);
        float lse = m + logf(expf(v0 - m) + expf(v1 - m));
        *reinterpret_cast<float2*>(out + 2 * i) = make_float2(v0 - lse, v1 - lse);
    }
}

extern "C" void kernel_launch(void* const* d_in, const int* in_sizes, int n_in,
                              void* d_out, int out_size) {
    const float* x  = (const float*)d_in[0];
    const int*   ei = (const int*)d_in[1];
    const float* W1 = (const float*)d_in[2];
    const float* b1 = (const float*)d_in[3];
    const float* W2 = (const float*)d_in[4];
    const float* b2 = (const float*)d_in[5];
    float* out = (float*)d_out;

    int n  = in_sizes[0];          // N nodes (x is [N,1])
    int ne = in_sizes[1] / 2;      // edge_index is [2, E]
    const int* src = ei;
    const int* dst = ei + ne;

    const int T = 256;
    int gridN  = (n + T - 1) / T;
    int gridN2 = (2 * n + T - 1) / T;
    int gridE4 = ((ne + 3) / 4 + T - 1) / T;

    k_init<<<gridN2, T>>>(n);
    k_count<<<gridE4, T>>>(dst, ne);
    k_prep<<<gridN, T>>>(x, n);
    k_scatter1<<<gridE4, T>>>(src, dst, ne);
    k_node<<<gridN, T>>>(W1, b1, W2, n);
    k_scatter2<<<gridE4, T>>>(src, dst, ne);
    k_final<<<gridN, T>>>(b2, out, n);
}

// round 2
// speedup vs baseline: 1.1901x; 1.1901x over previous
#include <cuda_runtime.h>
#include <math.h>

#define NN 500000
#define NE 8000000

// Scratch (device globals — no allocation in kernel_launch)
__device__ float g_deg[NN];
__device__ float g_dinv[NN];
__device__ float g_p[NN];            // x*dinv
__device__ float g_a1[NN];           // scatter accumulator layer 1
__device__ float2 g_q[NN];           // z*dinv per node (2 floats)
__device__ float2 g_a2[NN];          // scatter accumulator layer 2

// ---------------- init: deg=1 (self loop), a1=0, a2=0 ----------------
__global__ void k_init(int n) {
    int i = blockIdx.x * blockDim.x + threadIdx.x;
    if (i < n) {
        g_deg[i] = 1.0f;
        g_a1[i] = 0.0f;
        g_a2[i] = make_float2(0.0f, 0.0f);
    }
}

// ---------------- count in-degree over dst ----------------
__global__ void k_count(const int* __restrict__ dst, int ne) {
    int i = blockIdx.x * blockDim.x + threadIdx.x;
    int e = i * 4;
    if (e + 4 <= ne) {
        int4 d = *reinterpret_cast<const int4*>(dst + e);
        atomicAdd(&g_deg[d.x], 1.0f);
        atomicAdd(&g_deg[d.y], 1.0f);
        atomicAdd(&g_deg[d.z], 1.0f);
        atomicAdd(&g_deg[d.w], 1.0f);
    } else {
        for (; e < ne; e++) atomicAdd(&g_deg[dst[e]], 1.0f);
    }
}

// ---------------- dinv = rsqrt(deg); p = x * dinv ----------------
__global__ void k_prep(const float* __restrict__ x, int n) {
    int i = blockIdx.x * blockDim.x + threadIdx.x;
    if (i < n) {
        float dv = rsqrtf(g_deg[i]);
        g_dinv[i] = dv;
        g_p[i] = x[i] * dv;
    }
}

// ---------------- layer-1 scalar scatter: a1[dst] += p[src] ----------------
__global__ void k_scatter1(const int* __restrict__ src,
                           const int* __restrict__ dst, int ne) {
    int i = blockIdx.x * blockDim.x + threadIdx.x;
    int e = i * 4;
    if (e + 4 <= ne) {
        int4 s = *reinterpret_cast<const int4*>(src + e);
        int4 d = *reinterpret_cast<const int4*>(dst + e);
        float p0 = g_p[s.x], p1 = g_p[s.y], p2 = g_p[s.z], p3 = g_p[s.w];
        atomicAdd(&g_a1[d.x], p0);
        atomicAdd(&g_a1[d.y], p1);
        atomicAdd(&g_a1[d.z], p2);
        atomicAdd(&g_a1[d.w], p3);
    } else {
        for (; e < ne; e++) atomicAdd(&g_a1[dst[e]], g_p[src[e]]);
    }
}

// ---------------- per-node MLP: s1 -> relu(s1*W1+b1) @ W2 -> q = z*dinv ----
__global__ void k_node(const float* __restrict__ W1,
                       const float* __restrict__ b1,
                       const float* __restrict__ W2, int n) {
    __shared__ float sW1[16], sb1[16], sW2[32];
    int t = threadIdx.x;
    if (t < 16) { sW1[t] = W1[t]; sb1[t] = b1[t]; }
    if (t < 32) { sW2[t] = W2[t]; }
    __syncthreads();
    int i = blockIdx.x * blockDim.x + t;
    if (i < n) {
        float dv = g_dinv[i];
        float s1 = dv * (g_a1[i] + g_p[i]);
        float z0 = 0.0f, z1 = 0.0f;
        #pragma unroll
        for (int k = 0; k < 16; k++) {
            float h = fmaxf(fmaf(s1, sW1[k], sb1[k]), 0.0f);
            z0 = fmaf(h, sW2[2 * k + 0], z0);
            z1 = fmaf(h, sW2[2 * k + 1], z1);
        }
        g_q[i] = make_float2(z0 * dv, z1 * dv);
    }
}

// ---------------- layer-2 vector scatter: a2[dst] += q[src] (float2 RED) ----
__global__ void k_scatter2(const int* __restrict__ src,
                           const int* __restrict__ dst, int ne) {
    int i = blockIdx.x * blockDim.x + threadIdx.x;
    int e = i * 4;
    if (e + 4 <= ne) {
        int4 s = *reinterpret_cast<const int4*>(src + e);
        int4 d = *reinterpret_cast<const int4*>(dst + e);
        float2 q0 = g_q[s.x];
        float2 q1 = g_q[s.y];
        float2 q2 = g_q[s.z];
        float2 q3 = g_q[s.w];
        atomicAdd(&g_a2[d.x], q0);
        atomicAdd(&g_a2[d.y], q1);
        atomicAdd(&g_a2[d.z], q2);
        atomicAdd(&g_a2[d.w], q3);
    } else {
        for (; e < ne; e++) {
            atomicAdd(&g_a2[dst[e]], g_q[src[e]]);
        }
    }
}

// ---------------- finalize: out = log_softmax(dinv*(a2+q) + b2) ----------------
__global__ void k_final(const float* __restrict__ b2, float* __restrict__ out, int n) {
    int i = blockIdx.x * blockDim.x + threadIdx.x;
    if (i < n) {
        float dv = g_dinv[i];
        float2 q = g_q[i];
        float2 a = g_a2[i];
        float v0 = fmaf(dv, a.x + q.x, b2[0]);
        float v1 = fmaf(dv, a.y + q.y, b2[1]);
        float m = fmaxf(v0, v1);
        float lse = m + logf(expf(v0 - m) + expf(v1 - m));
        *reinterpret_cast<float2*>(out + 2 * i) = make_float2(v0 - lse, v1 - lse);
    }
}

extern "C" void kernel_launch(void* const* d_in, const int* in_sizes, int n_in,
                              void* d_out, int out_size) {
    const float* x  = (const float*)d_in[0];
    const int*   ei = (const int*)d_in[1];
    const float* W1 = (const float*)d_in[2];
    const float* b1 = (const float*)d_in[3];
    const float* W2 = (const float*)d_in[4];
    const float* b2 = (const float*)d_in[5];
    float* out = (float*)d_out;

    int n  = in_sizes[0];          // N nodes (x is [N,1])
    int ne = in_sizes[1] / 2;      // edge_index is [2, E]
    const int* src = ei;
    const int* dst = ei + ne;

    const int T = 256;
    int gridN  = (n + T - 1) / T;
    int gridE4 = ((ne + 3) / 4 + T - 1) / T;

    k_init<<<gridN, T>>>(n);
    k_count<<<gridE4, T>>>(dst, ne);
    k_prep<<<gridN, T>>>(x, n);
    k_scatter1<<<gridE4, T>>>(src, dst, ne);
    k_node<<<gridN, T>>>(W1, b1, W2, n);
    k_scatter2<<<gridE4, T>>>(src, dst, ne);
    k_final<<<gridN, T>>>(b2, out, n);
}